// round 4
// baseline (speedup 1.0000x reference)
#include <cuda_runtime.h>
#include <math.h>
#include <stdint.h>

#define D     1024
#define B     16
#define T     1024
#define G     128      // persistent CTAs (one per SM, all co-resident)
#define DPC   16       // output dims per CTA
#define BPC   8        // batches per CTA
#define NTHR  128      // threads per CTA (4 warps; warp w owns 4 d's)
#define XROW  10       // padded row length (floats) for [k][b] staging buffers

#define MAXR  0.999f
#define EPSF  1e-8f

// ---------------- device scratch (no allocation allowed) ----------------
__device__ float    g_WhT[D * D];       // W_h transposed (for power iteration)
__device__ float    g_hbuf[2][B * D];   // ping-pong hidden state
__device__ float    g_sigma;            // spectral norm estimate
__device__ unsigned g_bar;              // global barrier counter

// ---------------- packed fp32x2 helpers ----------------
__device__ __forceinline__ unsigned long long dup2(float w) {
    unsigned long long r;
    asm("mov.b64 %0, {%1, %1};" : "=l"(r) : "f"(w));
    return r;
}
__device__ __forceinline__ void fma2(unsigned long long& a, unsigned long long w,
                                     unsigned long long x) {
    asm("fma.rn.f32x2 %0, %1, %2, %0;" : "+l"(a) : "l"(w), "l"(x));
}
__device__ __forceinline__ unsigned long long addp(unsigned long long a,
                                                   unsigned long long b) {
    unsigned long long c;
    asm("add.rn.f32x2 %0, %1, %2;" : "=l"(c) : "l"(a), "l"(b));
    return c;
}

// ---------------- init: reset barrier, write h_all[0] = h0 ----------------
__global__ void k_init(const float* __restrict__ h0, float* __restrict__ hall0) {
    int i = blockIdx.x * blockDim.x + threadIdx.x;
    if (i == 0) g_bar = 0u;
    if (i < B * D) hall0[i] = h0[i];
}

// ---------------- tiled transpose: g_WhT = W_h^T ----------------
__global__ void k_transpose(const float* __restrict__ A) {
    __shared__ float tile[32][33];
    int bx = blockIdx.x * 32, by = blockIdx.y * 32;
    int tx = threadIdx.x, ty = threadIdx.y;   // block (32, 8)
#pragma unroll
    for (int r = 0; r < 32; r += 8)
        tile[ty + r][tx] = A[(size_t)(by + ty + r) * D + bx + tx];
    __syncthreads();
#pragma unroll
    for (int r = 0; r < 32; r += 8)
        g_WhT[(size_t)(bx + ty + r) * D + by + tx] = tile[tx][ty + r];
}

// ---------------- single-block power iteration + sigma ----------------
__device__ __forceinline__ float blk_reduce(float v, float* sred) {
#pragma unroll
    for (int s = 16; s; s >>= 1) v += __shfl_xor_sync(0xffffffffu, v, s);
    int w = threadIdx.x >> 5;
    if ((threadIdx.x & 31) == 0) sred[w] = v;
    __syncthreads();
    if (threadIdx.x < 32) {
        float r = sred[threadIdx.x];
#pragma unroll
        for (int s = 16; s; s >>= 1) r += __shfl_xor_sync(0xffffffffu, r, s);
        if (threadIdx.x == 0) sred[0] = r;
    }
    __syncthreads();
    float out = sred[0];
    __syncthreads();
    return out;
}

__global__ void k_power(const float* __restrict__ Wh, const float* __restrict__ u0) {
    __shared__ float sv[D];
    __shared__ float sred[32];
    const int tid = threadIdx.x;   // 1024 threads
    float u = u0[tid];
    float v = 0.f;

    for (int it = 0; it < 3; ++it) {
        // v = normalize(Wh^T u):  v_i = sum_j Wh[j,i] * u_j   (coalesced over i)
        sv[tid] = u;
        __syncthreads();
        float acc = 0.f;
#pragma unroll 8
        for (int j = 0; j < D; ++j) acc += Wh[(size_t)j * D + tid] * sv[j];
        __syncthreads();
        float nn = blk_reduce(acc * acc, sred);
        v = acc / (sqrtf(nn) + EPSF);

        // u = normalize(Wh v):  u_i = sum_j WhT[j,i] * v_j   (coalesced over i)
        sv[tid] = v;
        __syncthreads();
        acc = 0.f;
#pragma unroll 8
        for (int j = 0; j < D; ++j) acc += g_WhT[(size_t)j * D + tid] * sv[j];
        __syncthreads();
        nn = blk_reduce(acc * acc, sred);
        u = acc / (sqrtf(nn) + EPSF);
    }

    // sigma = | u . (Wh v) |
    sv[tid] = v;
    __syncthreads();
    float tvec = 0.f;
#pragma unroll 8
    for (int j = 0; j < D; ++j) tvec += g_WhT[(size_t)j * D + tid] * sv[j];
    __syncthreads();
    float s = blk_reduce(u * tvec, sred);
    if (tid == 0) g_sigma = fabsf(s);
}

// ---------------- staging: src[16][1024] rows b0..b0+7 -> dst[k][b] ----------------
__device__ __forceinline__ void stage_bk(float* __restrict__ dst,
                                         const float* __restrict__ src, int b0) {
    const int b = threadIdx.x >> 4;        // 0..7
    const int l16 = threadIdx.x & 15;
    const float* srow = src + (size_t)(b0 + b) * D;
#pragma unroll
    for (int i = 0; i < 16; ++i) {
        int k = l16 * 4 + i * 64;
        float4 vv = *(const float4*)(srow + k);
        dst[(k + 0) * XROW + b] = vv.x;
        dst[(k + 1) * XROW + b] = vv.y;
        dst[(k + 2) * XROW + b] = vv.z;
        dst[(k + 3) * XROW + b] = vv.w;
    }
}

// ---------------- core accumulate: acc[dd][bp] += W[d][k] * V2[k][bpair] ----------------
__device__ __forceinline__ void mv_loop(const float* __restrict__ W,
                                        const float* __restrict__ V,
                                        unsigned long long* acc, int dbase, int lane) {
#pragma unroll 4
    for (int i = 0; i < 32; ++i) {
        int k = lane + 32 * i;
        const float* vr = V + k * XROW;
        unsigned long long x0 = *(const unsigned long long*)(vr + 0);
        unsigned long long x1 = *(const unsigned long long*)(vr + 2);
        unsigned long long x2 = *(const unsigned long long*)(vr + 4);
        unsigned long long x3 = *(const unsigned long long*)(vr + 6);
#pragma unroll
        for (int dd = 0; dd < 4; ++dd) {
            unsigned long long w = dup2(W[(dbase + dd) * D + k]);
            fma2(acc[dd * 4 + 0], w, x0);
            fma2(acc[dd * 4 + 1], w, x1);
            fma2(acc[dd * 4 + 2], w, x2);
            fma2(acc[dd * 4 + 3], w, x3);
        }
    }
}

// ---------------- persistent fused recurrence kernel ----------------
__global__ void __launch_bounds__(NTHR, 1)
k_persist(const float* __restrict__ x, const float* __restrict__ z,
          const float* __restrict__ h0, const float* __restrict__ Wx,
          const float* __restrict__ Wh, const float* __restrict__ logr,
          const float* __restrict__ bias, float* __restrict__ out) {
    extern __shared__ float sm[];
    float* Wx_s  = sm;                    // [DPC][D]
    float* Wh_s  = Wx_s + DPC * D;        // [DPC][D] (pre-scaled)
    float* x_s   = Wh_s + DPC * D;        // [D][XROW]
    float* h_s   = x_s + D * XROW;        // [D][XROW]
    float* out_s = h_s + D * XROW;        // [DPC*BPC]

    const int cta = blockIdx.x;
    const int d0 = (cta >> 1) * DPC;
    const int b0 = (cta & 1) * BPC;
    const int tid = threadIdx.x;
    const int wid = tid >> 5;            // 0..3
    const int lane = tid & 31;
    const int dbase = wid * 4;           // this warp's local d-base

    // ---- load weight tiles; scale W_h rows by radii[d]/(sigma+eps) ----
    const float sig = g_sigma + EPSF;
    for (int i = tid; i < DPC * D / 4; i += NTHR) {
        int idx = i * 4;
        int dd = idx >> 10;
        int k = idx & (D - 1);
        int dglob = d0 + dd;
        float4 a = *(const float4*)(Wx + (size_t)dglob * D + k);
        *(float4*)(Wx_s + dd * D + k) = a;
        float r = (MAXR / (1.f + expf(-logr[dglob]))) / sig;
        float4 m = *(const float4*)(Wh + (size_t)dglob * D + k);
        m.x *= r; m.y *= r; m.z *= r; m.w *= r;
        *(float4*)(Wh_s + dd * D + k) = m;
    }
    __syncthreads();

    float* outs_ptr = out;                        // [T][B][D]
    float* hall_ptr = out + (size_t)T * B * D;    // [T+1][B][D]

    // epilogue mapping: consecutive tid -> consecutive d (coalesced stores)
    const int dl = tid & 15;
    const int bl = tid >> 4;
    const size_t eoff = (size_t)(b0 + bl) * D + (d0 + dl);
    const float my_bias = bias[d0 + dl];

    unsigned long long acc[16];   // [dd(4)][bpair(4)]

    // ---- step 0 x-part (no dependency on h) ----
    stage_bk(x_s, x, b0);
    __syncthreads();
#pragma unroll
    for (int i = 0; i < 16; ++i) acc[i] = 0ull;
    mv_loop(Wx_s, x_s, acc, dbase, lane);
    float zreg = z[eoff];

    for (int t = 0; t < T; ++t) {
        // ---- wait for step t-1 (h_prev ready chip-wide) ----
        if (t > 0) {
            if (tid == 0) {
                volatile unsigned* bp = &g_bar;
                unsigned target = (unsigned)t * G;
                while (*bp < target) {}
                __threadfence();
            }
            __syncthreads();
        }

        // ---- stage h_prev into [k][b] layout ----
        const float* hsrc = (t == 0) ? h0 : g_hbuf[(t - 1) & 1];
        stage_bk(h_s, hsrc, b0);
        __syncthreads();

        // ---- recurrent part: acc += W_heff * h_prev ----
        mv_loop(Wh_s, h_s, acc, dbase, lane);

        // ---- in-warp k reduction (packed adds) ----
#pragma unroll
        for (int i = 0; i < 16; ++i) {
            unsigned long long a = acc[i];
            a = addp(a, __shfl_xor_sync(0xffffffffu, a, 16));
            a = addp(a, __shfl_xor_sync(0xffffffffu, a, 8));
            a = addp(a, __shfl_xor_sync(0xffffffffu, a, 4));
            a = addp(a, __shfl_xor_sync(0xffffffffu, a, 2));
            a = addp(a, __shfl_xor_sync(0xffffffffu, a, 1));
            acc[i] = a;
        }
        if (lane == 0) {
#pragma unroll
            for (int dd = 0; dd < 4; ++dd)
#pragma unroll
                for (int bp = 0; bp < 4; ++bp) {
                    unsigned long long a = acc[dd * 4 + bp];
                    out_s[(dbase + dd) * 8 + 2 * bp]     = __uint_as_float((unsigned)(a & 0xffffffffull));
                    out_s[(dbase + dd) * 8 + 2 * bp + 1] = __uint_as_float((unsigned)(a >> 32));
                }
        }
        __syncthreads();

        // ---- epilogue: tanh, hidden-state publish, silu-gated output ----
        {
            float pre = out_s[dl * 8 + bl] + my_bias;
            float hnew = tanhf(pre);
            g_hbuf[t & 1][eoff] = hnew;
            float sil = zreg / (1.f + __expf(-zreg));
            outs_ptr[(size_t)t * B * D + eoff] = hnew * sil;
            hall_ptr[(size_t)(t + 1) * B * D + eoff] = hnew;
        }
        __syncthreads();

        // ---- arrive (release h_new chip-wide) ----
        if (tid == 0) {
            __threadfence();
            atomicAdd(&g_bar, 1u);
        }

        // ---- hide barrier latency: compute x-part of step t+1 ----
#pragma unroll
        for (int i = 0; i < 16; ++i) acc[i] = 0ull;
        if (t + 1 < T) {
            stage_bk(x_s, x + (size_t)(t + 1) * B * D, b0);
            __syncthreads();
            mv_loop(Wx_s, x_s, acc, dbase, lane);
            zreg = z[(size_t)(t + 1) * B * D + eoff];
        }
    }
}

// ---------------- launch ----------------
extern "C" void kernel_launch(void* const* d_in, const int* in_sizes, int n_in,
                              void* d_out, int out_size) {
    const float* x    = (const float*)d_in[0];
    const float* z    = (const float*)d_in[1];
    const float* h0   = (const float*)d_in[2];
    const float* Wx   = (const float*)d_in[3];
    const float* Wh   = (const float*)d_in[4];
    const float* logr = (const float*)d_in[5];
    const float* bias = (const float*)d_in[6];
    const float* u0   = (const float*)d_in[7];
    float* out = (float*)d_out;

    const int smem_bytes = (DPC * D * 2 + D * XROW * 2 + DPC * BPC) * sizeof(float);
    cudaFuncSetAttribute(k_persist, cudaFuncAttributeMaxDynamicSharedMemorySize,
                         smem_bytes);

    // h_all[0] = h0, barrier reset
    k_init<<<64, 256>>>(h0, out + (size_t)T * B * D);
    // W_h transpose for coalesced power iteration
    k_transpose<<<dim3(D / 32, D / 32), dim3(32, 8)>>>(Wh);
    // 3-step power iteration + sigma
    k_power<<<1, D>>>(Wh, u0);
    // fused persistent recurrence
    k_persist<<<G, NTHR, smem_bytes>>>(x, z, h0, Wx, Wh, logr, bias, out);
}

// round 5
// speedup vs baseline: 1.3784x; 1.3784x over previous
#include <cuda_runtime.h>
#include <math.h>
#include <stdint.h>

#define D     1024
#define B     16
#define T     1024
#define G     128      // persistent CTAs (one per SM)
#define DPC   16       // d's per CTA
#define BPC   8        // b's per CTA
#define NTHR  256      // 8 warps: 2 d-groups (8d) x 4 k-slices (256k)

#define MAXR  0.999f
#define EPSF  1e-8f

typedef unsigned long long u64;

// ---------------- device scratch ----------------
__device__ float    g_WhT[D * D];
__device__ float    g_hbuf[2][B * D];
__device__ float    g_sigma;
__device__ unsigned g_bar;

// ---------------- packed fp32x2 helpers ----------------
__device__ __forceinline__ u64 dup2(float w) {
    u64 r; asm("mov.b64 %0, {%1, %1};" : "=l"(r) : "f"(w)); return r;
}
__device__ __forceinline__ u64 pack2(float lo, float hi) {
    u64 r; asm("mov.b64 %0, {%1, %2};" : "=l"(r) : "f"(lo), "f"(hi)); return r;
}
__device__ __forceinline__ void fma2(u64& a, u64 w, u64 x) {
    asm("fma.rn.f32x2 %0, %1, %2, %0;" : "+l"(a) : "l"(w), "l"(x));
}
__device__ __forceinline__ u64 addp(u64 a, u64 b) {
    u64 c; asm("add.rn.f32x2 %0, %1, %2;" : "=l"(c) : "l"(a), "l"(b)); return c;
}
__device__ __forceinline__ float lo32(u64 a) { return __uint_as_float((unsigned)(a & 0xffffffffull)); }
__device__ __forceinline__ float hi32(u64 a) { return __uint_as_float((unsigned)(a >> 32)); }

// ---------------- init ----------------
__global__ void k_init(const float* __restrict__ h0, float* __restrict__ hall0) {
    int i = blockIdx.x * blockDim.x + threadIdx.x;
    if (i == 0) g_bar = 0u;
    if (i < B * D) hall0[i] = h0[i];
}

// ---------------- transpose for power iteration ----------------
__global__ void k_transpose(const float* __restrict__ A) {
    __shared__ float tile[32][33];
    int bx = blockIdx.x * 32, by = blockIdx.y * 32;
    int tx = threadIdx.x, ty = threadIdx.y;
#pragma unroll
    for (int r = 0; r < 32; r += 8)
        tile[ty + r][tx] = A[(size_t)(by + ty + r) * D + bx + tx];
    __syncthreads();
#pragma unroll
    for (int r = 0; r < 32; r += 8)
        g_WhT[(size_t)(bx + ty + r) * D + by + tx] = tile[tx][ty + r];
}

// ---------------- power iteration ----------------
__device__ __forceinline__ float blk_reduce(float v, float* sred) {
#pragma unroll
    for (int s = 16; s; s >>= 1) v += __shfl_xor_sync(0xffffffffu, v, s);
    int w = threadIdx.x >> 5;
    if ((threadIdx.x & 31) == 0) sred[w] = v;
    __syncthreads();
    if (threadIdx.x < 32) {
        float r = sred[threadIdx.x];
#pragma unroll
        for (int s = 16; s; s >>= 1) r += __shfl_xor_sync(0xffffffffu, r, s);
        if (threadIdx.x == 0) sred[0] = r;
    }
    __syncthreads();
    float out = sred[0];
    __syncthreads();
    return out;
}

__global__ void k_power(const float* __restrict__ Wh, const float* __restrict__ u0) {
    __shared__ float sv[D];
    __shared__ float sred[32];
    const int tid = threadIdx.x;
    float u = u0[tid];
    float v = 0.f;
    for (int it = 0; it < 3; ++it) {
        sv[tid] = u; __syncthreads();
        float acc = 0.f;
#pragma unroll 8
        for (int j = 0; j < D; ++j) acc += Wh[(size_t)j * D + tid] * sv[j];
        __syncthreads();
        float nn = blk_reduce(acc * acc, sred);
        v = acc / (sqrtf(nn) + EPSF);

        sv[tid] = v; __syncthreads();
        acc = 0.f;
#pragma unroll 8
        for (int j = 0; j < D; ++j) acc += g_WhT[(size_t)j * D + tid] * sv[j];
        __syncthreads();
        nn = blk_reduce(acc * acc, sred);
        u = acc / (sqrtf(nn) + EPSF);
    }
    sv[tid] = v; __syncthreads();
    float tvec = 0.f;
#pragma unroll 8
    for (int j = 0; j < D; ++j) tvec += g_WhT[(size_t)j * D + tid] * sv[j];
    __syncthreads();
    float s = blk_reduce(u * tvec, sred);
    if (tid == 0) g_sigma = fabsf(s);
}

// ---------------- conflict-free natural [b][k] staging ----------------
__device__ __forceinline__ void stage_rows(float* __restrict__ dst,
                                           const float* __restrict__ src,
                                           int b0, int tid) {
    const int b = tid >> 5, l = tid & 31;
    const float* s = src + (size_t)(b0 + b) * D;
    float* d = dst + b * D;
#pragma unroll
    for (int i = 0; i < 8; ++i) {
        int k = 4 * l + 128 * i;
        *(float4*)(d + k) = *(const float4*)(s + k);
    }
}

// ---------------- core GEMV tile: 8d x 8b per warp, 64B LDS per fma2 ----------------
__device__ __forceinline__ void mv8x8(const float* __restrict__ W,  // [DPC][D]
                                      const float* __restrict__ V,  // [BPC][D]
                                      u64* __restrict__ acc,
                                      int dbase, int kbase, int lane) {
#pragma unroll
    for (int i = 0; i < 8; ++i) {
        const int k = kbase + 32 * i + lane;
        float xv0 = V[0 * D + k], xv1 = V[1 * D + k];
        float xv2 = V[2 * D + k], xv3 = V[3 * D + k];
        float xv4 = V[4 * D + k], xv5 = V[5 * D + k];
        float xv6 = V[6 * D + k], xv7 = V[7 * D + k];
        u64 x0 = pack2(xv0, xv1);
        u64 x1 = pack2(xv2, xv3);
        u64 x2 = pack2(xv4, xv5);
        u64 x3 = pack2(xv6, xv7);
#pragma unroll
        for (int dd = 0; dd < 8; ++dd) {
            u64 w = dup2(W[(dbase + dd) * D + k]);
            fma2(acc[dd * 4 + 0], w, x0);
            fma2(acc[dd * 4 + 1], w, x1);
            fma2(acc[dd * 4 + 2], w, x2);
            fma2(acc[dd * 4 + 3], w, x3);
        }
    }
}

// distributing tree reduce: lane L ends owning sum-over-lanes of acc[L]
#define RED_LEVEL(m, n)                                                     \
    {                                                                       \
        const bool up = (lane & (m)) != 0;                                  \
        _Pragma("unroll")                                                   \
        for (int j = 0; j < (n); ++j) {                                     \
            u64 send = up ? acc[j] : acc[j + (n)];                          \
            u64 recv = __shfl_xor_sync(0xffffffffu, send, (m));             \
            acc[j] = addp(up ? acc[j + (n)] : acc[j], recv);                \
        }                                                                   \
    }

// ---------------- persistent fused recurrence ----------------
__global__ void __launch_bounds__(NTHR, 1)
k_persist(const float* __restrict__ x, const float* __restrict__ z,
          const float* __restrict__ h0, const float* __restrict__ Wx,
          const float* __restrict__ Wh, const float* __restrict__ logr,
          const float* __restrict__ bias, float* __restrict__ out) {
    extern __shared__ float sm[];
    float* Wx_s  = sm;                     // [DPC][D]   64 KB
    float* Wh_s  = Wx_s + DPC * D;         // [DPC][D]   64 KB (pre-scaled)
    float* x_s   = Wh_s + DPC * D;         // [BPC][D]   32 KB
    float* h_s   = x_s + BPC * D;          // [BPC][D]   32 KB
    u64*   red_s = (u64*)(h_s + BPC * D);  // [4][64]     2 KB

    const int cta = blockIdx.x;
    const int d0 = (cta >> 1) * DPC;
    const int b0 = (cta & 1) * BPC;
    const int tid = threadIdx.x;
    const int wid = tid >> 5;             // 0..7
    const int lane = tid & 31;
    const int dg = wid >> 2;              // d-group 0/1
    const int ks = wid & 3;               // k-slice 0..3
    const int dbase = dg * 8;             // local d base (8 d's)
    const int kbase = ks * 256;

    // ---- load weight tiles; pre-scale W_h rows ----
    const float sig = g_sigma + EPSF;
    for (int i = tid; i < DPC * D / 4; i += NTHR) {
        int idx = i * 4;
        int dd = idx >> 10;
        int k = idx & (D - 1);
        int dglob = d0 + dd;
        *(float4*)(Wx_s + dd * D + k) = *(const float4*)(Wx + (size_t)dglob * D + k);
        float r = (MAXR / (1.f + expf(-logr[dglob]))) / sig;
        float4 m = *(const float4*)(Wh + (size_t)dglob * D + k);
        m.x *= r; m.y *= r; m.z *= r; m.w *= r;
        *(float4*)(Wh_s + dd * D + k) = m;
    }

    float* outs_ptr = out;                        // [T][B][D]
    float* hall_ptr = out + (size_t)T * B * D;    // [T+1][B][D]

    // epilogue mapping: tid<128 -> one (d,b) float, consecutive tid = consecutive d
    const int dl = tid & 15;
    const int bl = (tid >> 4) & 7;
    const size_t eoff = (size_t)(b0 + bl) * D + (d0 + dl);
    const float my_bias = bias[d0 + dl];
    const int epi_dg = dl >> 3, epi_dd = dl & 7, epi_bp = bl >> 1, epi_half = bl & 1;
    const int epi_p = epi_dg * 32 + epi_dd * 4 + epi_bp;

    u64 acc[32];

    // ---- step 0 x-part (independent of h) ----
    stage_rows(x_s, x, b0, tid);
    __syncthreads();
#pragma unroll
    for (int i = 0; i < 32; ++i) acc[i] = 0ull;
    mv8x8(Wx_s, x_s, acc, dbase, kbase, lane);
    float zreg = (tid < 128) ? z[eoff] : 0.f;

    for (int t = 0; t < T; ++t) {
        // ---- chip-wide wait for step t-1 ----
        if (t > 0) {
            if (tid == 0) {
                volatile unsigned* bp = &g_bar;
                unsigned target = (unsigned)t * G;
                while (*bp < target) {}
                __threadfence();
            }
            __syncthreads();
        }

        // ---- stage h_prev (natural layout, conflict-free) ----
        const float* hsrc = (t == 0) ? h0 : g_hbuf[(t - 1) & 1];
        stage_rows(h_s, hsrc, b0, tid);
        __syncthreads();

        // ---- recurrent GEMV: acc += W_heff * h_prev ----
        mv8x8(Wh_s, h_s, acc, dbase, kbase, lane);

        // ---- tree reduce: lane L owns acc[L] ----
        RED_LEVEL(16, 16)
        RED_LEVEL(8, 8)
        RED_LEVEL(4, 4)
        RED_LEVEL(2, 2)
        RED_LEVEL(1, 1)
        red_s[ks * 64 + dg * 32 + lane] = acc[0];
        __syncthreads();

        // ---- epilogue: sum k-slices, tanh, publish, gate ----
        if (tid < 128) {
            u64 s01 = addp(red_s[0 * 64 + epi_p], red_s[1 * 64 + epi_p]);
            u64 s23 = addp(red_s[2 * 64 + epi_p], red_s[3 * 64 + epi_p]);
            u64 s = addp(s01, s23);
            float pre = (epi_half ? hi32(s) : lo32(s)) + my_bias;
            float hnew = tanhf(pre);
            g_hbuf[t & 1][eoff] = hnew;
            float sil = zreg / (1.f + __expf(-zreg));
            outs_ptr[(size_t)t * B * D + eoff] = hnew * sil;
            hall_ptr[(size_t)(t + 1) * B * D + eoff] = hnew;
        }
        __syncthreads();

        // ---- arrive ----
        if (tid == 0) {
            __threadfence();
            atomicAdd(&g_bar, 1u);
        }

        // ---- shadow work: x-part of step t+1 ----
#pragma unroll
        for (int i = 0; i < 32; ++i) acc[i] = 0ull;
        if (t + 1 < T) {
            stage_rows(x_s, x + (size_t)(t + 1) * B * D, b0, tid);
            __syncthreads();
            mv8x8(Wx_s, x_s, acc, dbase, kbase, lane);
            if (tid < 128) zreg = z[(size_t)(t + 1) * B * D + eoff];
        }
    }
}

// ---------------- launch ----------------
extern "C" void kernel_launch(void* const* d_in, const int* in_sizes, int n_in,
                              void* d_out, int out_size) {
    const float* x    = (const float*)d_in[0];
    const float* z    = (const float*)d_in[1];
    const float* h0   = (const float*)d_in[2];
    const float* Wx   = (const float*)d_in[3];
    const float* Wh   = (const float*)d_in[4];
    const float* logr = (const float*)d_in[5];
    const float* bias = (const float*)d_in[6];
    const float* u0   = (const float*)d_in[7];
    float* out = (float*)d_out;

    const int smem_bytes = (DPC * D * 2 + BPC * D * 2) * sizeof(float) + 256 * sizeof(u64);
    cudaFuncSetAttribute(k_persist, cudaFuncAttributeMaxDynamicSharedMemorySize,
                         smem_bytes);

    k_init<<<64, 256>>>(h0, out + (size_t)T * B * D);
    k_transpose<<<dim3(D / 32, D / 32), dim3(32, 8)>>>(Wh);
    k_power<<<1, D>>>(Wh, u0);
    k_persist<<<G, NTHR, smem_bytes>>>(x, z, h0, Wx, Wh, logr, bias, out);
}